// round 15
// baseline (speedup 1.0000x reference)
#include <cuda_runtime.h>
#include <cuda_fp16.h>
#include <cstdint>

#define Nn 2048
#define Mm 10
#define Dd 256
#define ROWS (Nn * Mm)      // 20480

// ---------------------------------------------------------------------------
// Scratch (device globals; no allocation allowed)
// ---------------------------------------------------------------------------
__device__ __align__(16) __half g_A[(size_t)ROWS * Dd];  // normalized emb, fp16
__device__ __align__(16) __half g_B[(size_t)Nn * Dd];    // normalized centroids, fp16
__device__ float g_rowsum[ROWS];
__device__ float g_pos[ROWS];   // stores t = |w|*(cos-1); shift cancels in lse-pos

__device__ __forceinline__ uint32_t smem_u32(const void* p) {
    uint32_t a;
    asm("{ .reg .u64 t; cvta.to.shared.u64 t, %1; cvt.u32.u64 %0, t; }" : "=r"(a) : "l"(p));
    return a;
}
__device__ __forceinline__ void cpa16(uint32_t dst, const void* src) {
    asm volatile("cp.async.cg.shared.global [%0], [%1], 16;" :: "r"(dst), "l"(src));
}
__device__ __forceinline__ void ldm_x4(uint32_t* r, uint32_t addr) {
    asm volatile("ldmatrix.sync.aligned.m8n8.x4.shared.b16 {%0,%1,%2,%3}, [%4];"
                 : "=r"(r[0]), "=r"(r[1]), "=r"(r[2]), "=r"(r[3]) : "r"(addr));
}
__device__ __forceinline__ void mma_f16acc(uint32_t* c, const uint32_t* a,
                                           uint32_t b0, uint32_t b1) {
    asm volatile(
        "mma.sync.aligned.m16n8k16.row.col.f16.f16.f16.f16 "
        "{%0,%1}, {%2,%3,%4,%5}, {%6,%7}, {%0,%1};"
        : "+r"(c[0]), "+r"(c[1])
        : "r"(a[0]), "r"(a[1]), "r"(a[2]), "r"(a[3]), "r"(b0), "r"(b1));
}
__device__ __forceinline__ float wred32(float v) {
#pragma unroll
    for (int off = 16; off > 0; off >>= 1) v += __shfl_xor_sync(0xffffffffu, v, off);
    return v;
}

// ---------------------------------------------------------------------------
// Kernel 1: prep, warp-per-speaker, registers only (R12 version — proven
// 10.3us), but 128-thread blocks (grid 512) for finer wave packing.
// ---------------------------------------------------------------------------
__global__ void __launch_bounds__(128) prep_kernel(const float* __restrict__ emb,
                                                   const float* __restrict__ wp) {
    const int warp = threadIdx.x >> 5, lane = threadIdx.x & 31;
    const int n = blockIdx.x * 4 + warp;

    float4 x[Mm][2];
    const float* src = emb + (size_t)n * Mm * Dd + lane * 8;
#pragma unroll
    for (int m = 0; m < Mm; m++) {
        x[m][0] = *(const float4*)(src + m * Dd);
        x[m][1] = *(const float4*)(src + m * Dd + 4);
    }

    float sc[Mm];
#pragma unroll
    for (int m = 0; m < Mm; m++) {
        float4 a = x[m][0], b = x[m][1];
        float ss = a.x * a.x + a.y * a.y + a.z * a.z + a.w * a.w
                 + b.x * b.x + b.y * b.y + b.z * b.z + b.w * b.w;
        ss = wred32(ss);
        sc[m] = 1.f / fmaxf(sqrtf(ss), 1e-12f);
    }

#pragma unroll
    for (int m = 0; m < Mm; m++) {
        float4 a = x[m][0], b = x[m][1];
        float s = sc[m];
        __half2 p0 = __floats2half2_rn(a.x * s, a.y * s);
        __half2 p1 = __floats2half2_rn(a.z * s, a.w * s);
        __half2 p2 = __floats2half2_rn(b.x * s, b.y * s);
        __half2 p3 = __floats2half2_rn(b.z * s, b.w * s);
        uint4 v{*(uint32_t*)&p0, *(uint32_t*)&p1, *(uint32_t*)&p2, *(uint32_t*)&p3};
        *(uint4*)(g_A + (size_t)(n * Mm + m) * Dd + lane * 8) = v;
    }

    float s0 = 0, s1 = 0, s2 = 0, s3 = 0, s4 = 0, s5 = 0, s6 = 0, s7 = 0;
#pragma unroll
    for (int m = 0; m < Mm; m++) {
        s0 += x[m][0].x; s1 += x[m][0].y; s2 += x[m][0].z; s3 += x[m][0].w;
        s4 += x[m][1].x; s5 += x[m][1].y; s6 += x[m][1].z; s7 += x[m][1].w;
    }
    float cs = wred32(s0 * s0 + s1 * s1 + s2 * s2 + s3 * s3
                    + s4 * s4 + s5 * s5 + s6 * s6 + s7 * s7);
    float cinv = 1.f / fmaxf(sqrtf(cs), 1e-12f);
    {
        __half2 p0 = __floats2half2_rn(s0 * cinv, s1 * cinv);
        __half2 p1 = __floats2half2_rn(s2 * cinv, s3 * cinv);
        __half2 p2 = __floats2half2_rn(s4 * cinv, s5 * cinv);
        __half2 p3 = __floats2half2_rn(s6 * cinv, s7 * cinv);
        uint4 v{*(uint32_t*)&p0, *(uint32_t*)&p1, *(uint32_t*)&p2, *(uint32_t*)&p3};
        *(uint4*)(g_B + (size_t)n * Dd + lane * 8) = v;
    }

    const float wabs = fabsf(*wp);
#pragma unroll
    for (int m = 0; m < Mm; m++) {
        float4 a = x[m][0], b = x[m][1];
        float d = a.x * s0 + a.y * s1 + a.z * s2 + a.w * s3
                + b.x * s4 + b.y * s5 + b.z * s6 + b.w * s7;
        d = wred32(d);
        if (lane == 0) g_pos[n * Mm + m] = wabs * (d * sc[m] * cinv - 1.f);
    }
    if (lane < Mm) g_rowsum[n * Mm + lane] = 0.f;
}

// ---------------------------------------------------------------------------
// Kernel 2: fp16 HMMA (fp16 acc), CTA tile 128x128, 4 warps (2x2), warp tile
// 64x64, BK=32, 2-stage cp.async pipeline. __launch_bounds__(128,5): 102 regs
// -> 5 CTAs/SM = 20 warps/SM (R13 profile: tensor 53%, latency-bound at 16).
// ---------------------------------------------------------------------------
#define BK 32
#define SSTR 40                       // padded row stride (elems); 80B
#define NCHUNK (Dd / BK)              // 8
#define STG (128 * SSTR * 2)          // 10240 B per tile stage

__global__ void __launch_bounds__(128, 5)
gemm_lse_kernel(const float* __restrict__ wp) {
    __shared__ __half smem[2 * 2 * STG / 2];   // 40960 B: [A0 A1 | B0 B1]
    const uint32_t as0 = smem_u32(smem);
    const uint32_t bs0 = as0 + 2 * STG;

    const int tid = threadIdx.x;
    const int wid = tid >> 5, lane = tid & 31;
    const int wm = wid >> 1;
    const int wn = wid & 1;
    const int r0 = blockIdx.y * 128;
    const int c0 = blockIdx.x * 128;

    const int lrow = tid >> 2;
    const int lquad = tid & 3;

    auto load_chunk = [&](int c, int stg) {
#pragma unroll
        for (int i = 0; i < 4; i++) {
            int row = lrow + i * 32;
            cpa16(as0 + stg * STG + row * (SSTR * 2) + lquad * 16,
                  g_A + (size_t)(r0 + row) * Dd + c * BK + lquad * 8);
            cpa16(bs0 + stg * STG + row * (SSTR * 2) + lquad * 16,
                  g_B + (size_t)(c0 + row) * Dd + c * BK + lquad * 8);
        }
        asm volatile("cp.async.commit_group;" ::: "memory");
    };

    uint32_t acc[4][8][2] = {};

    load_chunk(0, 0);
    load_chunk(1, 1);

#pragma unroll
    for (int c = 0; c < NCHUNK; c++) {
        if (c < 7) asm volatile("cp.async.wait_group 1;" ::: "memory");
        else       asm volatile("cp.async.wait_group 0;" ::: "memory");
        __syncthreads();

        const uint32_t ab = as0 + (c & 1) * STG;
        const uint32_t bb = bs0 + (c & 1) * STG;
#pragma unroll
        for (int ks = 0; ks < 2; ks++) {
            const int k0 = ks * 16;
            uint32_t a[4][4];
#pragma unroll
            for (int mt = 0; mt < 4; mt++) {
                int row = wm * 64 + mt * 16 + (lane & 15);
                int col = k0 + (lane >> 4) * 8;
                ldm_x4(a[mt], ab + row * (SSTR * 2) + col * 2);
            }
            uint32_t b[4][4];
#pragma unroll
            for (int ng = 0; ng < 4; ng++) {
                int row = wn * 64 + ng * 16 + (lane & 7) + (lane >> 4) * 8;
                int col = k0 + ((lane >> 3) & 1) * 8;
                ldm_x4(b[ng], bb + row * (SSTR * 2) + col * 2);
            }
#pragma unroll
            for (int mt = 0; mt < 4; mt++)
#pragma unroll
                for (int nt = 0; nt < 8; nt++)
                    mma_f16acc(acc[mt][nt], a[mt],
                               b[nt >> 1][(nt & 1) * 2], b[nt >> 1][(nt & 1) * 2 + 1]);
        }
        __syncthreads();
        if (c + 2 < NCHUNK) load_chunk(c + 2, c & 1);
    }

    const float wabs = fabsf(*wp);
    const float nw = -wabs;
    const int q = lane >> 2, qi = lane & 3;

#pragma unroll
    for (int mt = 0; mt < 4; mt++) {
        const int rowA = r0 + wm * 64 + mt * 16 + q;
        const int rowB = rowA + 8;
        float sA = 0.f, sB = 0.f;
#pragma unroll
        for (int nt = 0; nt < 8; nt++) {
            float2 vA = __half22float2(*(__half2*)&acc[mt][nt][0]);
            float2 vB = __half22float2(*(__half2*)&acc[mt][nt][1]);
            sA += __expf(fmaf(wabs, vA.x, nw)) + __expf(fmaf(wabs, vA.y, nw));
            sB += __expf(fmaf(wabs, vB.x, nw)) + __expf(fmaf(wabs, vB.y, nw));
        }
#pragma unroll
        for (int off = 2; off > 0; off >>= 1) {
            sA += __shfl_xor_sync(0xffffffffu, sA, off);
            sB += __shfl_xor_sync(0xffffffffu, sB, off);
        }
        if (qi == 0) {
            atomicAdd(&g_rowsum[rowA], sA);
            atomicAdd(&g_rowsum[rowB], sB);
        }
    }
}

// ---------------------------------------------------------------------------
// Kernel 3: loss = mean_r( log(rowsum[r]) - pos_t[r] ), 1024 thr, vectorized.
// ---------------------------------------------------------------------------
__global__ void __launch_bounds__(1024) loss_kernel(float* __restrict__ out) {
    __shared__ float red[32];
    const int tid = threadIdx.x;
    float s = 0.f;
#pragma unroll
    for (int i = 0; i < ROWS / 4096; i++) {
        int r4 = tid + i * 1024;
        float4 rs = *(const float4*)&g_rowsum[r4 * 4];
        float4 ps = *(const float4*)&g_pos[r4 * 4];
        s += __logf(rs.x) - ps.x + __logf(rs.y) - ps.y
           + __logf(rs.z) - ps.z + __logf(rs.w) - ps.w;
    }
#pragma unroll
    for (int off = 16; off > 0; off >>= 1) s += __shfl_xor_sync(0xffffffffu, s, off);
    if ((tid & 31) == 0) red[tid >> 5] = s;
    __syncthreads();
    if (tid < 32) {
        float t = red[tid];
#pragma unroll
        for (int off = 16; off > 0; off >>= 1) t += __shfl_xor_sync(0xffffffffu, t, off);
        if (tid == 0) out[0] = t / (float)ROWS;
    }
}

// ---------------------------------------------------------------------------
extern "C" void kernel_launch(void* const* d_in, const int* in_sizes, int n_in,
                              void* d_out, int out_size) {
    const float* emb = (const float*)d_in[0];
    const float* w   = (const float*)d_in[1];
    const float* b   = (const float*)d_in[2];
    (void)b;
    float* out = (float*)d_out;

    prep_kernel<<<Nn / 4, 128>>>(emb, w);
    gemm_lse_kernel<<<dim3(Nn / 128, ROWS / 128), 128>>>(w);
    loss_kernel<<<1, 1024>>>(out);
}

// round 16
// speedup vs baseline: 1.4140x; 1.4140x over previous
#include <cuda_runtime.h>
#include <cuda_fp16.h>
#include <cstdint>

#define Nn 2048
#define Mm 10
#define Dd 256
#define ROWS (Nn * Mm)      // 20480

// ---------------------------------------------------------------------------
// Scratch (device globals; no allocation allowed)
// ---------------------------------------------------------------------------
__device__ __align__(16) __half g_A[(size_t)ROWS * Dd];  // normalized emb, fp16
__device__ __align__(16) __half g_B[(size_t)Nn * Dd];    // normalized centroids, fp16
__device__ float g_rowsum[ROWS];
__device__ float g_pos[ROWS];   // stores t = |w|*(cos-1); shift cancels in lse-pos

__device__ __forceinline__ uint32_t smem_u32(const void* p) {
    uint32_t a;
    asm("{ .reg .u64 t; cvta.to.shared.u64 t, %1; cvt.u32.u64 %0, t; }" : "=r"(a) : "l"(p));
    return a;
}
__device__ __forceinline__ void cpa16(uint32_t dst, const void* src) {
    asm volatile("cp.async.cg.shared.global [%0], [%1], 16;" :: "r"(dst), "l"(src));
}
__device__ __forceinline__ void ldm_x4(uint32_t* r, uint32_t addr) {
    asm volatile("ldmatrix.sync.aligned.m8n8.x4.shared.b16 {%0,%1,%2,%3}, [%4];"
                 : "=r"(r[0]), "=r"(r[1]), "=r"(r[2]), "=r"(r[3]) : "r"(addr));
}
__device__ __forceinline__ void mma_f16acc(uint32_t* c, const uint32_t* a,
                                           uint32_t b0, uint32_t b1) {
    asm volatile(
        "mma.sync.aligned.m16n8k16.row.col.f16.f16.f16.f16 "
        "{%0,%1}, {%2,%3,%4,%5}, {%6,%7}, {%0,%1};"
        : "+r"(c[0]), "+r"(c[1])
        : "r"(a[0]), "r"(a[1]), "r"(a[2]), "r"(a[3]), "r"(b0), "r"(b1));
}
__device__ __forceinline__ float wred32(float v) {
#pragma unroll
    for (int off = 16; off > 0; off >>= 1) v += __shfl_xor_sync(0xffffffffu, v, off);
    return v;
}

// ---------------------------------------------------------------------------
// Kernel 1: prep, warp-per-speaker, registers only (R12-exact, proven 10.3us).
// ---------------------------------------------------------------------------
__global__ void __launch_bounds__(256) prep_kernel(const float* __restrict__ emb,
                                                   const float* __restrict__ wp) {
    const int warp = threadIdx.x >> 5, lane = threadIdx.x & 31;
    const int n = blockIdx.x * 8 + warp;

    float4 x[Mm][2];
    const float* src = emb + (size_t)n * Mm * Dd + lane * 8;
#pragma unroll
    for (int m = 0; m < Mm; m++) {
        x[m][0] = *(const float4*)(src + m * Dd);
        x[m][1] = *(const float4*)(src + m * Dd + 4);
    }

    float sc[Mm];
#pragma unroll
    for (int m = 0; m < Mm; m++) {
        float4 a = x[m][0], b = x[m][1];
        float ss = a.x * a.x + a.y * a.y + a.z * a.z + a.w * a.w
                 + b.x * b.x + b.y * b.y + b.z * b.z + b.w * b.w;
        ss = wred32(ss);
        sc[m] = 1.f / fmaxf(sqrtf(ss), 1e-12f);
    }

#pragma unroll
    for (int m = 0; m < Mm; m++) {
        float4 a = x[m][0], b = x[m][1];
        float s = sc[m];
        __half2 p0 = __floats2half2_rn(a.x * s, a.y * s);
        __half2 p1 = __floats2half2_rn(a.z * s, a.w * s);
        __half2 p2 = __floats2half2_rn(b.x * s, b.y * s);
        __half2 p3 = __floats2half2_rn(b.z * s, b.w * s);
        uint4 v{*(uint32_t*)&p0, *(uint32_t*)&p1, *(uint32_t*)&p2, *(uint32_t*)&p3};
        *(uint4*)(g_A + (size_t)(n * Mm + m) * Dd + lane * 8) = v;
    }

    float s0 = 0, s1 = 0, s2 = 0, s3 = 0, s4 = 0, s5 = 0, s6 = 0, s7 = 0;
#pragma unroll
    for (int m = 0; m < Mm; m++) {
        s0 += x[m][0].x; s1 += x[m][0].y; s2 += x[m][0].z; s3 += x[m][0].w;
        s4 += x[m][1].x; s5 += x[m][1].y; s6 += x[m][1].z; s7 += x[m][1].w;
    }
    float cs = wred32(s0 * s0 + s1 * s1 + s2 * s2 + s3 * s3
                    + s4 * s4 + s5 * s5 + s6 * s6 + s7 * s7);
    float cinv = 1.f / fmaxf(sqrtf(cs), 1e-12f);
    {
        __half2 p0 = __floats2half2_rn(s0 * cinv, s1 * cinv);
        __half2 p1 = __floats2half2_rn(s2 * cinv, s3 * cinv);
        __half2 p2 = __floats2half2_rn(s4 * cinv, s5 * cinv);
        __half2 p3 = __floats2half2_rn(s6 * cinv, s7 * cinv);
        uint4 v{*(uint32_t*)&p0, *(uint32_t*)&p1, *(uint32_t*)&p2, *(uint32_t*)&p3};
        *(uint4*)(g_B + (size_t)n * Dd + lane * 8) = v;
    }

    const float wabs = fabsf(*wp);
#pragma unroll
    for (int m = 0; m < Mm; m++) {
        float4 a = x[m][0], b = x[m][1];
        float d = a.x * s0 + a.y * s1 + a.z * s2 + a.w * s3
                + b.x * s4 + b.y * s5 + b.z * s6 + b.w * s7;
        d = wred32(d);
        if (lane == 0) g_pos[n * Mm + m] = wabs * (d * sc[m] * cinv - 1.f);
    }
    if (lane < Mm) g_rowsum[n * Mm + lane] = 0.f;
}

// ---------------------------------------------------------------------------
// Kernel 2: fp16 HMMA (fp16 acc), CTA tile 128x128, 4 warps (2x2), warp tile
// 64x64, BK=32, 3-stage cp.async pipeline with ONE sync per chunk.
// Unpadded 64B rows + XOR swizzle (chunk ^= (row>>1)&3): conflict-free and
// stage = 8192B -> 49152B static smem -> 4 CTAs/SM.
// ---------------------------------------------------------------------------
#define BK 32
#define NCHUNK (Dd / BK)              // 8
#define STG 8192                      // 128 rows x 64B per tile stage

__device__ __forceinline__ uint32_t swz(int row, int chunk) {
    return (uint32_t)(row * 64 + ((chunk ^ ((row >> 1) & 3)) * 16));
}

__global__ void __launch_bounds__(128, 4)
gemm_lse_kernel(const float* __restrict__ wp) {
    __shared__ __half smem[6 * STG / 2];   // 49152 B: [A0 A1 A2 | B0 B1 B2]
    const uint32_t as0 = smem_u32(smem);
    const uint32_t bs0 = as0 + 3 * STG;

    const int tid = threadIdx.x;
    const int wid = tid >> 5, lane = tid & 31;
    const int wm = wid >> 1;
    const int wn = wid & 1;
    const int r0 = blockIdx.y * 128;
    const int c0 = blockIdx.x * 128;

    const int lrow = tid >> 2;        // 0..31
    const int lquad = tid & 3;

    auto load_chunk = [&](int c, int stg) {
#pragma unroll
        for (int i = 0; i < 4; i++) {
            int row = lrow + i * 32;
            uint32_t off = swz(row, lquad);
            cpa16(as0 + stg * STG + off,
                  g_A + (size_t)(r0 + row) * Dd + c * BK + lquad * 8);
            cpa16(bs0 + stg * STG + off,
                  g_B + (size_t)(c0 + row) * Dd + c * BK + lquad * 8);
        }
        asm volatile("cp.async.commit_group;" ::: "memory");
    };

    uint32_t acc[4][8][2] = {};

    load_chunk(0, 0);
    load_chunk(1, 1);

#pragma unroll
    for (int c = 0; c < NCHUNK; c++) {
        if (c < 7) asm volatile("cp.async.wait_group 1;" ::: "memory");
        else       asm volatile("cp.async.wait_group 0;" ::: "memory");
        __syncthreads();               // single barrier: data ready + stage free
        if (c + 2 < NCHUNK) load_chunk(c + 2, (c + 2) % 3);

        const uint32_t ab = as0 + (c % 3) * STG;
        const uint32_t bb = bs0 + (c % 3) * STG;
#pragma unroll
        for (int ks = 0; ks < 2; ks++) {
            uint32_t a[4][4];
#pragma unroll
            for (int mt = 0; mt < 4; mt++) {
                int row = wm * 64 + mt * 16 + (lane & 15);
                int chunk = ks * 2 + (lane >> 4);
                ldm_x4(a[mt], ab + swz(row, chunk));
            }
            uint32_t b[4][4];
#pragma unroll
            for (int ng = 0; ng < 4; ng++) {
                int row = wn * 64 + ng * 16 + (lane & 7) + (lane >> 4) * 8;
                int chunk = ks * 2 + ((lane >> 3) & 1);
                ldm_x4(b[ng], bb + swz(row, chunk));
            }
#pragma unroll
            for (int mt = 0; mt < 4; mt++)
#pragma unroll
                for (int nt = 0; nt < 8; nt++)
                    mma_f16acc(acc[mt][nt], a[mt],
                               b[nt >> 1][(nt & 1) * 2], b[nt >> 1][(nt & 1) * 2 + 1]);
        }
    }

    const float wabs = fabsf(*wp);
    const float nw = -wabs;
    const int q = lane >> 2, qi = lane & 3;

#pragma unroll
    for (int mt = 0; mt < 4; mt++) {
        const int rowA = r0 + wm * 64 + mt * 16 + q;
        const int rowB = rowA + 8;
        float sA = 0.f, sB = 0.f;
#pragma unroll
        for (int nt = 0; nt < 8; nt++) {
            float2 vA = __half22float2(*(__half2*)&acc[mt][nt][0]);
            float2 vB = __half22float2(*(__half2*)&acc[mt][nt][1]);
            sA += __expf(fmaf(wabs, vA.x, nw)) + __expf(fmaf(wabs, vA.y, nw));
            sB += __expf(fmaf(wabs, vB.x, nw)) + __expf(fmaf(wabs, vB.y, nw));
        }
#pragma unroll
        for (int off = 2; off > 0; off >>= 1) {
            sA += __shfl_xor_sync(0xffffffffu, sA, off);
            sB += __shfl_xor_sync(0xffffffffu, sB, off);
        }
        if (qi == 0) {
            atomicAdd(&g_rowsum[rowA], sA);
            atomicAdd(&g_rowsum[rowB], sB);
        }
    }
}

// ---------------------------------------------------------------------------
// Kernel 3: loss = mean_r( log(rowsum[r]) - pos_t[r] ), 1024 thr, vectorized.
// ---------------------------------------------------------------------------
__global__ void __launch_bounds__(1024) loss_kernel(float* __restrict__ out) {
    __shared__ float red[32];
    const int tid = threadIdx.x;
    float s = 0.f;
#pragma unroll
    for (int i = 0; i < ROWS / 4096; i++) {
        int r4 = tid + i * 1024;
        float4 rs = *(const float4*)&g_rowsum[r4 * 4];
        float4 ps = *(const float4*)&g_pos[r4 * 4];
        s += __logf(rs.x) - ps.x + __logf(rs.y) - ps.y
           + __logf(rs.z) - ps.z + __logf(rs.w) - ps.w;
    }
#pragma unroll
    for (int off = 16; off > 0; off >>= 1) s += __shfl_xor_sync(0xffffffffu, s, off);
    if ((tid & 31) == 0) red[tid >> 5] = s;
    __syncthreads();
    if (tid < 32) {
        float t = red[tid];
#pragma unroll
        for (int off = 16; off > 0; off >>= 1) t += __shfl_xor_sync(0xffffffffu, t, off);
        if (tid == 0) out[0] = t / (float)ROWS;
    }
}

// ---------------------------------------------------------------------------
extern "C" void kernel_launch(void* const* d_in, const int* in_sizes, int n_in,
                              void* d_out, int out_size) {
    const float* emb = (const float*)d_in[0];
    const float* w   = (const float*)d_in[1];
    const float* b   = (const float*)d_in[2];
    (void)b;
    float* out = (float*)d_out;

    prep_kernel<<<Nn / 8, 256>>>(emb, w);
    gemm_lse_kernel<<<dim3(Nn / 128, ROWS / 128), 128>>>(w);
    loss_kernel<<<1, 1024>>>(out);
}